// round 1
// baseline (speedup 1.0000x reference)
#include <cuda_runtime.h>

// DTCWT 1D forward, 3 levels, fully fused.
// x: [64, 1, 2^20] f32. Outputs concatenated in tuple order:
//   lo  [64,1,131072]      @ 0
//   yh0 [64,1,1,524288]    @ 8388608
//   yh1 [64,2,1,262144]    @ 41943040
//   yh2 [64,2,1,131072]    @ 75497472

#define L0    (1 << 20)
#define L1LEN (L0 >> 1)   // 524288
#define L2LEN (L0 >> 2)   // 262144
#define L3LEN (L0 >> 3)   // 131072
#define BATCH 64

#define TILE_X 4096
#define N1 2048
#define N2 1024
#define N3 512
#define XH 52
#define XLEN (TILE_X + 2 * XH)   // 4200
#define H1 24
#define LO1LEN (N1 + 2 * H1)     // 2096
#define H2 8
#define LO2LEN (N2 + 2 * H2)     // 1040
#define NTH 256

#define OUT_YH0 8388608u
#define OUT_YH1 41943040u
#define OUT_YH2 75497472u

// ---- filters as compile-time immediates (fixed in reference setup_inputs) ----
static __device__ __forceinline__ float conv5_h0o(const float* v) {
    float s = -0.05f * v[0];
    s = fmaf(0.25f, v[1], s);
    s = fmaf(0.6f,  v[2], s);
    s = fmaf(0.25f, v[3], s);
    s = fmaf(-0.05f, v[4], s);
    return s;
}
static __device__ __forceinline__ float conv7_h1o(const float* v) {
    float s = -0.0107143f * v[0];
    s = fmaf( 0.0535714f, v[1], s);
    s = fmaf( 0.2607143f, v[2], s);
    s = fmaf(-0.6071429f, v[3], s);
    s = fmaf( 0.2607143f, v[4], s);
    s = fmaf( 0.0535714f, v[5], s);
    s = fmaf(-0.0107143f, v[6], s);
    return s;
}
static __device__ __forceinline__ float conv14_h0a(const float* v) {
    float s =  0.00325314f * v[0];
    s = fmaf(-0.00388321f, v[1],  s);
    s = fmaf( 0.03466035f, v[2],  s);
    s = fmaf(-0.03887280f, v[3],  s);
    s = fmaf(-0.11720389f, v[4],  s);
    s = fmaf( 0.27529538f, v[5],  s);
    s = fmaf( 0.75614564f, v[6],  s);
    s = fmaf( 0.56881042f, v[7],  s);
    s = fmaf( 0.01186609f, v[8],  s);
    s = fmaf(-0.10671180f, v[9],  s);
    s = fmaf( 0.02382538f, v[10], s);
    s = fmaf( 0.01702522f, v[11], s);
    s = fmaf(-0.00543948f, v[12], s);
    s = fmaf(-0.00455690f, v[13], s);
    return s;
}
// h1a[n] = (-1)^n * h0a[13-n]
static __device__ __forceinline__ float conv14_h1a(const float* v) {
    float s = -0.00455690f * v[0];
    s = fmaf( 0.00543948f, v[1],  s);
    s = fmaf( 0.01702522f, v[2],  s);
    s = fmaf(-0.02382538f, v[3],  s);
    s = fmaf(-0.10671180f, v[4],  s);
    s = fmaf(-0.01186609f, v[5],  s);
    s = fmaf( 0.56881042f, v[6],  s);
    s = fmaf(-0.75614564f, v[7],  s);
    s = fmaf( 0.27529538f, v[8],  s);
    s = fmaf( 0.11720389f, v[9],  s);
    s = fmaf(-0.03887280f, v[10], s);
    s = fmaf(-0.03466035f, v[11], s);
    s = fmaf(-0.00388321f, v[12], s);
    s = fmaf(-0.00325314f, v[13], s);
    return s;
}
// h1b = reverse(h1a)
static __device__ __forceinline__ float conv14_h1b(const float* v) {
    float s = -0.00325314f * v[0];
    s = fmaf(-0.00388321f, v[1],  s);
    s = fmaf(-0.03466035f, v[2],  s);
    s = fmaf(-0.03887280f, v[3],  s);
    s = fmaf( 0.11720389f, v[4],  s);
    s = fmaf( 0.27529538f, v[5],  s);
    s = fmaf(-0.75614564f, v[6],  s);
    s = fmaf( 0.56881042f, v[7],  s);
    s = fmaf(-0.01186609f, v[8],  s);
    s = fmaf(-0.10671180f, v[9],  s);
    s = fmaf(-0.02382538f, v[10], s);
    s = fmaf( 0.01702522f, v[11], s);
    s = fmaf( 0.00543948f, v[12], s);
    s = fmaf(-0.00455690f, v[13], s);
    return s;
}

// load 14 contiguous floats starting at even smem index via 7x LDS.64
static __device__ __forceinline__ void load14(const float* base_even, float* w) {
    const float2* p = (const float2*)base_even;
#pragma unroll
    for (int t = 0; t < 7; t++) {
        float2 q = p[t];
        w[2 * t]     = q.x;
        w[2 * t + 1] = q.y;
    }
}

__global__ __launch_bounds__(NTH) void dtcwt_kernel(const float* __restrict__ x,
                                                    float* __restrict__ out) {
    __shared__ __align__(16) float sx[XLEN];     // x tile (+halo); reused as lo2 later
    __shared__ __align__(16) float slo1[LO1LEN];

    const int tile = blockIdx.x;   // 0..255
    const int b    = blockIdx.y;   // 0..63
    const int tid  = threadIdx.x;

    const float* xrow = x + (size_t)b * L0;
    const int gx0 = tile * TILE_X - XH;

    // ---- load x tile with global zero padding ----
    for (int i = tid; i < XLEN; i += NTH) {
        int g = gx0 + i;
        sx[i] = ((unsigned)g < (unsigned)L0) ? xrow[g] : 0.0f;
    }
    __syncthreads();

    // ---- Level 1: lo1 (5-tap h0o) into smem, hi (7-tap h1o) to gmem ----
    const int base1 = tile * N1;
    float* yh0 = out + OUT_YH0 + (size_t)b * L1LEN + base1;

    // lo1 halo (48 entries), zero outside the level-1 domain
    if (tid < 2 * H1) {
        int r  = (tid < H1) ? tid : tid + N1;       // [0,H1) U [N1+H1, N1+2H1)
        int g1 = base1 - H1 + r;
        float v = 0.0f;
        if ((unsigned)g1 < (unsigned)L1LEN) v = conv5_h0o(sx + 2 * r + 2);
        slo1[r] = v;
    }
    // main: shared float2 loads serve both lo1[m+H1] and hi[m]
    for (int m = tid; m < N1; m += NTH) {
        float w[8];
        const float2* p = (const float2*)(sx + 2 * m + 48);  // even, 8B aligned
#pragma unroll
        for (int t = 0; t < 4; t++) {
            float2 q = p[t];
            w[2 * t]     = q.x;
            w[2 * t + 1] = q.y;
        }
        slo1[m + H1] = conv5_h0o(w + 2);   // x[2m+50 .. 2m+54]
        yh0[m]       = conv7_h1o(w + 1);   // x[2m+49 .. 2m+55]
    }
    __syncthreads();

    // ---- Level 2: lo2 (h0a) into smem (aliases sx), hia/hib to gmem ----
    float* lo2 = sx;
    const int base2 = tile * N2;
    float* yh1 = out + OUT_YH1 + (size_t)b * (2u * L2LEN) + base2;

    if (tid < 2 * H2) {
        int r  = (tid < H2) ? tid : tid + N2;
        int g2 = base2 - H2 + r;
        float v = 0.0f;
        if ((unsigned)g2 < (unsigned)L2LEN) {
            float w[14];
            load14(slo1 + 2 * r + 2, w);
            v = conv14_h0a(w);
        }
        lo2[r] = v;
    }
    for (int m = tid; m < N2; m += NTH) {
        float w[14];
        load14(slo1 + 2 * m + 18, w);      // lo1[2m-6 .. 2m+7] (+H1 offset)
        lo2[m + H2]    = conv14_h0a(w);
        yh1[m]         = conv14_h1a(w);
        yh1[m + L2LEN] = conv14_h1b(w);
    }
    __syncthreads();

    // ---- Level 3: lo, hia/hib to gmem ----
    const int base3 = tile * N3;
    float* olo = out + (size_t)b * L3LEN + base3;
    float* yh2 = out + OUT_YH2 + (size_t)b * (2u * L3LEN) + base3;

    for (int m = tid; m < N3; m += NTH) {
        float w[14];
        load14(lo2 + 2 * m + 2, w);
        olo[m]         = conv14_h0a(w);
        yh2[m]         = conv14_h1a(w);
        yh2[m + L3LEN] = conv14_h1b(w);
    }
}

extern "C" void kernel_launch(void* const* d_in, const int* in_sizes, int n_in,
                              void* d_out, int out_size) {
    const float* x = (const float*)d_in[0];
    float* out = (float*)d_out;
    dim3 grid(L0 / TILE_X, BATCH);
    dtcwt_kernel<<<grid, NTH>>>(x, out);
}

// round 3
// speedup vs baseline: 1.5016x; 1.5016x over previous
#include <cuda_runtime.h>

// DTCWT 1D forward, 3 levels, fully fused. x: [64, 1, 2^20] f32.
// Outputs concatenated: lo @0, yh0 @8388608, yh1 @41943040, yh2 @75497472.

#define L0    (1 << 20)
#define L1LEN (L0 >> 1)   // 524288
#define L2LEN (L0 >> 2)   // 262144
#define L3LEN (L0 >> 3)   // 131072
#define BATCH 64

#define TILE_X 8192
#define TILES  (L0 / TILE_X)       // 128
#define N1 (TILE_X / 2)            // 4096
#define N2 (TILE_X / 4)            // 2048
#define N3 (TILE_X / 8)            // 1024
#define XH 52
#define XLEN (TILE_X + 2 * XH)     // 8296
#define H1 24
#define LO1LEN (N1 + 2 * H1)       // 4144
#define H2 8
#define NTH 256

#define SX_SIZE 8320               // sx region padded to mult of 128 floats
#define SM_TOTAL (SX_SIZE + LO1LEN)

#define OUT_YH0 8388608u
#define OUT_YH1 41943040u
#define OUT_YH2 75497472u

// bank swizzle: XOR float-index bits [2,3] with bits [5,6] (16B-unit granular)
__device__ __forceinline__ int SW(int i) { return i ^ ((i >> 3) & 0xC); }

// ---- filters as compile-time immediates (fixed in reference) ----
static __device__ __forceinline__ float conv5_h0o(const float* v) {
    float s = -0.05f * (v[0] + v[4]);
    s = fmaf(0.25f, v[1] + v[3], s);
    s = fmaf(0.6f, v[2], s);
    return s;
}
static __device__ __forceinline__ float conv7_h1o(const float* v) {
    float s = -0.0107143f * (v[0] + v[6]);
    s = fmaf( 0.0535714f, v[1] + v[5], s);
    s = fmaf( 0.2607143f, v[2] + v[4], s);
    s = fmaf(-0.6071429f, v[3], s);
    return s;
}
// h1a[n] = (-1)^n * h0a[13-n]
static __device__ __forceinline__ float conv14_h1a(const float* v) {
    float s = -0.00455690f * v[0];
    s = fmaf( 0.00543948f, v[1],  s);
    s = fmaf( 0.01702522f, v[2],  s);
    s = fmaf(-0.02382538f, v[3],  s);
    s = fmaf(-0.10671180f, v[4],  s);
    s = fmaf(-0.01186609f, v[5],  s);
    s = fmaf( 0.56881042f, v[6],  s);
    s = fmaf(-0.75614564f, v[7],  s);
    s = fmaf( 0.27529538f, v[8],  s);
    s = fmaf( 0.11720389f, v[9],  s);
    s = fmaf(-0.03887280f, v[10], s);
    s = fmaf(-0.03466035f, v[11], s);
    s = fmaf(-0.00388321f, v[12], s);
    s = fmaf(-0.00325314f, v[13], s);
    return s;
}
// lo = conv(h0a), hb = conv(h1b). h0a[j] = (-1)^(13-j)*h1b[j] =>
// lo = E + O, hb = O - E with E/O = even/odd-tap partial sums of h0a.
static __device__ __forceinline__ void conv14_lo_hb(const float* v, float& lo, float& hb) {
    float e =  0.00325314f * v[0];
    e = fmaf( 0.03466035f, v[2],  e);
    e = fmaf(-0.11720389f, v[4],  e);
    e = fmaf( 0.75614564f, v[6],  e);
    e = fmaf( 0.01186609f, v[8],  e);
    e = fmaf( 0.02382538f, v[10], e);
    e = fmaf(-0.00543948f, v[12], e);
    float o = -0.00388321f * v[1];
    o = fmaf(-0.03887280f, v[3],  o);
    o = fmaf( 0.27529538f, v[5],  o);
    o = fmaf( 0.56881042f, v[7],  o);
    o = fmaf(-0.10671180f, v[9],  o);
    o = fmaf( 0.01702522f, v[11], o);
    o = fmaf(-0.00455690f, v[13], o);
    lo = e + o;
    hb = o - e;
}
static __device__ __forceinline__ float conv14_h0a(const float* v) {
    float lo, hb;
    conv14_lo_hb(v, lo, hb);
    return lo;
}

// load 20 floats from swizzled smem, base index even but ≡2 mod 4
static __device__ __forceinline__ void load20(const float* buf, int bi, float* w) {
    *(float2*)(w)      = *(const float2*)(buf + SW(bi));
    *(float4*)(w + 2)  = *(const float4*)(buf + SW(bi + 2));
    *(float4*)(w + 6)  = *(const float4*)(buf + SW(bi + 6));
    *(float4*)(w + 10) = *(const float4*)(buf + SW(bi + 10));
    *(float4*)(w + 14) = *(const float4*)(buf + SW(bi + 14));
    *(float2*)(w + 18) = *(const float2*)(buf + SW(bi + 18));
}

__global__ __launch_bounds__(NTH, 4) void dtcwt_kernel(const float* __restrict__ x,
                                                       float* __restrict__ out) {
    __shared__ __align__(128) float sm[SM_TOTAL];
    float* sx   = sm;             // x tile (+halo); later aliased as lo2
    float* slo1 = sm + SX_SIZE;
    float* lo2  = sm;

    const int tile = blockIdx.x;   // 0..127
    const int b    = blockIdx.y;   // 0..63
    const int tid  = threadIdx.x;

    const float* xrow = x + (size_t)b * L0;
    const int gx0 = tile * TILE_X - XH;   // mult of 4

    // ---- load x tile ----
    if (tile > 0 && tile < TILES - 1) {
        const float4* xg = (const float4*)(xrow + gx0);
#pragma unroll
        for (int u = 0; u < (XLEN / 4 + NTH - 1) / NTH; u++) {
            int k = tid + u * NTH;
            if (k < XLEN / 4) {
                float4 v = __ldcs(xg + k);
                *(float4*)(sx + SW(4 * k)) = v;
            }
        }
    } else {
        for (int i = tid; i < XLEN; i += NTH) {
            int g = gx0 + i;
            sx[SW(i)] = ((unsigned)g < (unsigned)L0) ? __ldcs(xrow + g) : 0.0f;
        }
    }
    __syncthreads();

    // ---- Level 1 ----
    const int base1 = tile * N1;
    float* yh0 = out + OUT_YH0 + (size_t)b * L1LEN + base1;

    if (tid < 2 * H1) {   // lo1 halo (48 entries), zero outside level-1 domain
        int r  = (tid < H1) ? tid : tid + N1;
        int g1 = base1 + (r - H1);
        float v = 0.0f;
        if ((unsigned)g1 < (unsigned)L1LEN) {
            float w[5];
#pragma unroll
            for (int j = 0; j < 5; j++) w[j] = sx[SW(2 * r + 2 + j)];
            v = conv5_h0o(w);
        }
        slo1[SW(r)] = v;
    }
#pragma unroll
    for (int it = 0; it < N1 / (4 * NTH); it++) {   // 4 iters
        int m4 = 4 * tid + it * (4 * NTH);
        int bi = 2 * m4 + 48;                        // mult of 4
        float w[16];
        *(float4*)(w)      = *(const float4*)(sx + SW(bi));
        *(float4*)(w + 4)  = *(const float4*)(sx + SW(bi + 4));
        *(float4*)(w + 8)  = *(const float4*)(sx + SW(bi + 8));
        *(float4*)(w + 12) = *(const float4*)(sx + SW(bi + 12));
        float4 lo, hi;
        lo.x = conv5_h0o(w + 2); hi.x = conv7_h1o(w + 1);
        lo.y = conv5_h0o(w + 4); hi.y = conv7_h1o(w + 3);
        lo.z = conv5_h0o(w + 6); hi.z = conv7_h1o(w + 5);
        lo.w = conv5_h0o(w + 8); hi.w = conv7_h1o(w + 7);
        *(float4*)(slo1 + SW(m4 + H1)) = lo;
        __stcs((float4*)(yh0 + m4), hi);
    }
    __syncthreads();

    // ---- Level 2 ----
    const int base2 = tile * N2;
    float* yh1 = out + OUT_YH1 + (size_t)b * (2u * L2LEN) + base2;

    if (tid < 2 * H2) {   // lo2 halo (16 entries)
        int r  = (tid < H2) ? tid : tid + N2;
        int g2 = base2 + (r - H2);
        float v = 0.0f;
        if ((unsigned)g2 < (unsigned)L2LEN) {
            float w[14];
#pragma unroll
            for (int j = 0; j < 14; j++) w[j] = slo1[SW(2 * r + 2 + j)];
            v = conv14_h0a(w);
        }
        lo2[SW(r)] = v;
    }
#pragma unroll
    for (int it = 0; it < N2 / (4 * NTH); it++) {   // 2 iters
        int m4 = 4 * tid + it * (4 * NTH);
        int bi = 2 * m4 + 18;
        float w[20];
        load20(slo1, bi, w);
        float4 a, ha, hb;
        conv14_lo_hb(w,     a.x, hb.x); ha.x = conv14_h1a(w);
        conv14_lo_hb(w + 2, a.y, hb.y); ha.y = conv14_h1a(w + 2);
        conv14_lo_hb(w + 4, a.z, hb.z); ha.z = conv14_h1a(w + 4);
        conv14_lo_hb(w + 6, a.w, hb.w); ha.w = conv14_h1a(w + 6);
        __stcs((float4*)(yh1 + m4), ha);
        __stcs((float4*)(yh1 + m4 + L2LEN), hb);
        *(float4*)(lo2 + SW(m4 + H2)) = a;
    }
    __syncthreads();

    // ---- Level 3 ----
    const int base3 = tile * N3;
    float* olo = out + (size_t)b * L3LEN + base3;
    float* yh2 = out + OUT_YH2 + (size_t)b * (2u * L3LEN) + base3;
    {
        int m4 = 4 * tid;                 // N3 = 4*NTH exactly
        int bi = 2 * m4 + 2;
        float w[20];
        load20(lo2, bi, w);
        float4 a, ha, hb;
        conv14_lo_hb(w,     a.x, hb.x); ha.x = conv14_h1a(w);
        conv14_lo_hb(w + 2, a.y, hb.y); ha.y = conv14_h1a(w + 2);
        conv14_lo_hb(w + 4, a.z, hb.z); ha.z = conv14_h1a(w + 4);
        conv14_lo_hb(w + 6, a.w, hb.w); ha.w = conv14_h1a(w + 6);
        __stcs((float4*)(olo + m4), a);
        __stcs((float4*)(yh2 + m4), ha);
        __stcs((float4*)(yh2 + m4 + L3LEN), hb);
    }
}

extern "C" void kernel_launch(void* const* d_in, const int* in_sizes, int n_in,
                              void* d_out, int out_size) {
    const float* x = (const float*)d_in[0];
    float* out = (float*)d_out;
    dim3 grid(TILES, BATCH);
    dtcwt_kernel<<<grid, NTH>>>(x, out);
}